// round 2
// baseline (speedup 1.0000x reference)
#include <cuda_runtime.h>

// Problem shape (fixed by the reference setup_inputs)
#define BB 16
#define HH 1024
#define WW 1280

// Per-batch coefficients:
// [0..8]   M   (3x3, row-major)        : K R^T K^-1
// [9..11]  Wv  (3)                     : K R^T (-t)
// [12..14] M2 row 2 (3)                : row 2 of (K R) K^-1
// [15]     W2z                         : (K t)[2]
__device__ float g_coef[BB][16];

__global__ void precompute_kernel(const float* __restrict__ trans,
                                  const float* __restrict__ rot,
                                  const float* __restrict__ intr) {
    int b = threadIdx.x;
    if (b >= BB) return;

    float K[3][3];
    #pragma unroll
    for (int i = 0; i < 3; i++)
        #pragma unroll
        for (int j = 0; j < 3; j++)
            K[i][j] = intr[i * 3 + j];

    // analytic 3x3 inverse (adjugate)
    float a00 = K[1][1]*K[2][2] - K[1][2]*K[2][1];
    float a01 = K[0][2]*K[2][1] - K[0][1]*K[2][2];
    float a02 = K[0][1]*K[1][2] - K[0][2]*K[1][1];
    float a10 = K[1][2]*K[2][0] - K[1][0]*K[2][2];
    float a11 = K[0][0]*K[2][2] - K[0][2]*K[2][0];
    float a12 = K[0][2]*K[1][0] - K[0][0]*K[1][2];
    float a20 = K[1][0]*K[2][1] - K[1][1]*K[2][0];
    float a21 = K[0][1]*K[2][0] - K[0][0]*K[2][1];
    float a22 = K[0][0]*K[1][1] - K[0][1]*K[1][0];
    float det = K[0][0]*a00 + K[0][1]*a10 + K[0][2]*a20;
    float id  = 1.0f / det;
    float Ki[3][3] = {{a00*id, a01*id, a02*id},
                      {a10*id, a11*id, a12*id},
                      {a20*id, a21*id, a22*id}};

    float R[3][3];
    #pragma unroll
    for (int i = 0; i < 3; i++)
        #pragma unroll
        for (int j = 0; j < 3; j++)
            R[i][j] = rot[b * 9 + i * 3 + j];

    float t0 = trans[b * 3 + 0], t1 = trans[b * 3 + 1], t2 = trans[b * 3 + 2];

    // temp = K * R^T
    float T[3][3];
    #pragma unroll
    for (int i = 0; i < 3; i++)
        #pragma unroll
        for (int k = 0; k < 3; k++)
            T[i][k] = K[i][0]*R[k][0] + K[i][1]*R[k][1] + K[i][2]*R[k][2];

    // Wv = temp * (-t)
    float Wv[3];
    #pragma unroll
    for (int i = 0; i < 3; i++)
        Wv[i] = -(T[i][0]*t0 + T[i][1]*t1 + T[i][2]*t2);

    // M = temp * Kinv
    float M[3][3];
    #pragma unroll
    for (int i = 0; i < 3; i++)
        #pragma unroll
        for (int k = 0; k < 3; k++)
            M[i][k] = T[i][0]*Ki[0][k] + T[i][1]*Ki[1][k] + T[i][2]*Ki[2][k];

    // KR = K * R ; M2 row 2 = KR[2][:] * Kinv
    float KR2[3];
    #pragma unroll
    for (int k = 0; k < 3; k++)
        KR2[k] = K[2][0]*R[0][k] + K[2][1]*R[1][k] + K[2][2]*R[2][k];
    float M2r[3];
    #pragma unroll
    for (int k = 0; k < 3; k++)
        M2r[k] = KR2[0]*Ki[0][k] + KR2[1]*Ki[1][k] + KR2[2]*Ki[2][k];

    float W2z = K[2][0]*t0 + K[2][1]*t1 + K[2][2]*t2;

    float* c = g_coef[b];
    c[0] = M[0][0]; c[1] = M[0][1]; c[2] = M[0][2];
    c[3] = M[1][0]; c[4] = M[1][1]; c[5] = M[1][2];
    c[6] = M[2][0]; c[7] = M[2][1]; c[8] = M[2][2];
    c[9] = Wv[0];   c[10] = Wv[1];  c[11] = Wv[2];
    c[12] = M2r[0]; c[13] = M2r[1]; c[14] = M2r[2];
    c[15] = W2z;
}

__device__ __forceinline__ float corner_val(const float* __restrict__ d2b,
                                            int ix, int iy,
                                            float m20, float m21, float m22,
                                            float w2z) {
    float d2 = __ldg(d2b + iy * WW + ix);
    return fmaf(d2, fmaf(m20, (float)ix, fmaf(m21, (float)iy, m22)), w2z);
}

__global__ void __launch_bounds__(256)
depth_warp_kernel(const float* __restrict__ d1,
                  const float* __restrict__ d2,
                  float* __restrict__ out) {
    // each thread handles 4 consecutive x pixels
    long long tid = (long long)blockIdx.x * blockDim.x + threadIdx.x;
    long long pix = tid * 4;
    const long long total = (long long)BB * HH * WW;
    if (pix >= total) return;

    int x  = (int)(pix % WW);
    int y  = (int)((pix / WW) % HH);
    int b  = (int)(pix / ((long long)WW * HH));

    const float* c = g_coef[b];
    float m00 = __ldg(c + 0), m01 = __ldg(c + 1), m02 = __ldg(c + 2);
    float m10 = __ldg(c + 3), m11 = __ldg(c + 4), m12 = __ldg(c + 5);
    float m20 = __ldg(c + 6), m21 = __ldg(c + 7), m22 = __ldg(c + 8);
    float wv0 = __ldg(c + 9), wv1 = __ldg(c + 10), wv2 = __ldg(c + 11);
    float q20 = __ldg(c + 12), q21 = __ldg(c + 13), q22 = __ldg(c + 14);
    float w2z = __ldg(c + 15);

    const float* d2b = d2 + (long long)b * HH * WW;

    float4 z1v = *reinterpret_cast<const float4*>(d1 + pix);
    float z1a[4] = {z1v.x, z1v.y, z1v.z, z1v.w};
    float res[4];

    float fv = (float)y;
    // row-dependent partials
    float ry0 = fmaf(m01, fv, m02);
    float ry1 = fmaf(m11, fv, m12);
    float ry2 = fmaf(m21, fv, m22);

    #pragma unroll
    for (int i = 0; i < 4; i++) {
        float fu = (float)(x + i);
        float z1 = z1a[i];
        float z2 = fmaf(z1, fmaf(m20, fu, ry2), wv2);
        float nu = fmaf(z1, fmaf(m00, fu, ry0), wv0);
        float nv = fmaf(z1, fmaf(m10, fu, ry1), wv1);
        float inv = __fdividef(1.0f, z2);
        float u2 = nu * inv;
        float v2 = nv * inv;

        int ix0 = (int)floorf(u2);
        int iy0 = (int)floorf(v2);
        int ix1 = min(max(ix0 + 1, 0), WW - 1);
        int iy1 = min(max(iy0 + 1, 0), HH - 1);
        ix0 = min(max(ix0, 0), WW - 1);
        iy0 = min(max(iy0, 0), HH - 1);

        float x0f = (float)ix0, x1f = (float)ix1;
        float y0f = (float)iy0, y1f = (float)iy1;

        float wa = (x1f - u2) * (y1f - v2);
        float wb = (x1f - u2) * (v2 - y0f);
        float wc = (u2 - x0f) * (y1f - v2);
        float wd = (u2 - x0f) * (v2 - y0f);

        float Ia = corner_val(d2b, ix0, iy0, q20, q21, q22, w2z);
        float Ib = corner_val(d2b, ix0, iy1, q20, q21, q22, w2z);
        float Ic = corner_val(d2b, ix1, iy0, q20, q21, q22, w2z);
        float Id = corner_val(d2b, ix1, iy1, q20, q21, q22, w2z);

        res[i] = wa * Ia + wb * Ib + wc * Ic + wd * Id;
    }

    float4 o = make_float4(res[0], res[1], res[2], res[3]);
    *reinterpret_cast<float4*>(out + pix) = o;
}

extern "C" void kernel_launch(void* const* d_in, const int* in_sizes, int n_in,
                              void* d_out, int out_size) {
    const float* d1   = (const float*)d_in[0];
    const float* d2   = (const float*)d_in[1];
    const float* tr   = (const float*)d_in[2];
    const float* rot  = (const float*)d_in[3];
    const float* intr = (const float*)d_in[4];
    float* out = (float*)d_out;

    precompute_kernel<<<1, BB>>>(tr, rot, intr);

    const long long total = (long long)BB * HH * WW;   // 20,971,520
    const int threads = 256;
    const long long nthreads = total / 4;              // 5,242,880
    const int blocks = (int)((nthreads + threads - 1) / threads);
    depth_warp_kernel<<<blocks, threads>>>(d1, d2, out);
}

// round 3
// speedup vs baseline: 1.1563x; 1.1563x over previous
#include <cuda_runtime.h>

#define BB 16
#define HH 1024
#define WW 1280

// Per-batch coefficients:
// [0..8]   M   (3x3, row-major)        : K R^T K^-1
// [9..11]  Wv  (3)                     : K R^T (-t)
// [12..14] M2 row 2 (3)                : row 2 of (K R) K^-1
// [15]     W2z                         : (K t)[2]
__device__ float g_coef[BB][16];

__global__ void precompute_kernel(const float* __restrict__ trans,
                                  const float* __restrict__ rot,
                                  const float* __restrict__ intr) {
    int b = threadIdx.x;
    if (b >= BB) return;

    float K[3][3];
    #pragma unroll
    for (int i = 0; i < 3; i++)
        #pragma unroll
        for (int j = 0; j < 3; j++)
            K[i][j] = intr[i * 3 + j];

    float a00 = K[1][1]*K[2][2] - K[1][2]*K[2][1];
    float a01 = K[0][2]*K[2][1] - K[0][1]*K[2][2];
    float a02 = K[0][1]*K[1][2] - K[0][2]*K[1][1];
    float a10 = K[1][2]*K[2][0] - K[1][0]*K[2][2];
    float a11 = K[0][0]*K[2][2] - K[0][2]*K[2][0];
    float a12 = K[0][2]*K[1][0] - K[0][0]*K[1][2];
    float a20 = K[1][0]*K[2][1] - K[1][1]*K[2][0];
    float a21 = K[0][1]*K[2][0] - K[0][0]*K[2][1];
    float a22 = K[0][0]*K[1][1] - K[0][1]*K[1][0];
    float det = K[0][0]*a00 + K[0][1]*a10 + K[0][2]*a20;
    float id  = 1.0f / det;
    float Ki[3][3] = {{a00*id, a01*id, a02*id},
                      {a10*id, a11*id, a12*id},
                      {a20*id, a21*id, a22*id}};

    float R[3][3];
    #pragma unroll
    for (int i = 0; i < 3; i++)
        #pragma unroll
        for (int j = 0; j < 3; j++)
            R[i][j] = rot[b * 9 + i * 3 + j];

    float t0 = trans[b * 3 + 0], t1 = trans[b * 3 + 1], t2 = trans[b * 3 + 2];

    // temp = K * R^T
    float T[3][3];
    #pragma unroll
    for (int i = 0; i < 3; i++)
        #pragma unroll
        for (int k = 0; k < 3; k++)
            T[i][k] = K[i][0]*R[k][0] + K[i][1]*R[k][1] + K[i][2]*R[k][2];

    float Wv[3];
    #pragma unroll
    for (int i = 0; i < 3; i++)
        Wv[i] = -(T[i][0]*t0 + T[i][1]*t1 + T[i][2]*t2);

    float M[3][3];
    #pragma unroll
    for (int i = 0; i < 3; i++)
        #pragma unroll
        for (int k = 0; k < 3; k++)
            M[i][k] = T[i][0]*Ki[0][k] + T[i][1]*Ki[1][k] + T[i][2]*Ki[2][k];

    float KR2[3];
    #pragma unroll
    for (int k = 0; k < 3; k++)
        KR2[k] = K[2][0]*R[0][k] + K[2][1]*R[1][k] + K[2][2]*R[2][k];
    float M2r[3];
    #pragma unroll
    for (int k = 0; k < 3; k++)
        M2r[k] = KR2[0]*Ki[0][k] + KR2[1]*Ki[1][k] + KR2[2]*Ki[2][k];

    float W2z = K[2][0]*t0 + K[2][1]*t1 + K[2][2]*t2;

    float* c = g_coef[b];
    c[0] = M[0][0]; c[1] = M[0][1]; c[2] = M[0][2];
    c[3] = M[1][0]; c[4] = M[1][1]; c[5] = M[1][2];
    c[6] = M[2][0]; c[7] = M[2][1]; c[8] = M[2][2];
    c[9] = Wv[0];   c[10] = Wv[1];  c[11] = Wv[2];
    c[12] = M2r[0]; c[13] = M2r[1]; c[14] = M2r[2];
    c[15] = W2z;
}

__device__ __forceinline__ float corner_val(const float* __restrict__ rowp,
                                            int ix, float rowpart,
                                            float q20, float w2z) {
    float d2 = __ldg(rowp + ix);
    return fmaf(d2, fmaf(q20, (float)ix, rowpart), w2z);
}

// Layout: each warp owns a contiguous 128-pixel span within one image row
// (WW=1280 is a multiple of 128). Thread t processes pixels span+t+32*i.
// => every gather LDG has lanes hitting ~consecutive addresses (1-2 L1 lines).
__global__ void __launch_bounds__(256)
depth_warp_kernel(const float* __restrict__ d1,
                  const float* __restrict__ d2,
                  float* __restrict__ out) {
    const int lane = threadIdx.x & 31;
    const int wid  = threadIdx.x >> 5;
    const long long warp_global = (long long)blockIdx.x * 8 + wid;
    const long long span = warp_global * 128;          // first pixel of warp span

    int x0 = (int)(span % WW);                         // span start x (row-aligned chunks)
    int y  = (int)((span / WW) % HH);
    int b  = (int)(span / ((long long)WW * HH));

    const float* c = g_coef[b];
    float m00 = c[0], m01 = c[1], m02 = c[2];
    float m10 = c[3], m11 = c[4], m12 = c[5];
    float m20 = c[6], m21 = c[7], m22 = c[8];
    float wv0 = c[9], wv1 = c[10], wv2 = c[11];
    float q20 = c[12], q21 = c[13], q22 = c[14];
    float w2z = c[15];

    const float* d2b = d2 + (long long)b * HH * WW;

    float fv = (float)y;
    float ry0 = fmaf(m01, fv, m02);
    float ry1 = fmaf(m11, fv, m12);
    float ry2 = fmaf(m21, fv, m22);

    const long long base = span + lane;

    #pragma unroll
    for (int i = 0; i < 4; i++) {
        long long pix = base + 32 * i;
        float fu = (float)(x0 + lane + 32 * i);
        float z1 = __ldg(d1 + pix);

        float z2 = fmaf(z1, fmaf(m20, fu, ry2), wv2);
        float nu = fmaf(z1, fmaf(m00, fu, ry0), wv0);
        float nv = fmaf(z1, fmaf(m10, fu, ry1), wv1);
        float inv = __fdividef(1.0f, z2);
        float u2 = nu * inv;
        float v2 = nv * inv;

        int ix0 = (int)floorf(u2);
        int iy0 = (int)floorf(v2);
        int ix1 = min(max(ix0 + 1, 0), WW - 1);
        int iy1 = min(max(iy0 + 1, 0), HH - 1);
        ix0 = min(max(ix0, 0), WW - 1);
        iy0 = min(max(iy0, 0), HH - 1);

        float x0f = (float)ix0, x1f = (float)ix1;
        float y0f = (float)iy0, y1f = (float)iy1;

        float wa = (x1f - u2) * (y1f - v2);
        float wb = (x1f - u2) * (v2 - y0f);
        float wc = (u2 - x0f) * (y1f - v2);
        float wd = (u2 - x0f) * (v2 - y0f);

        const float* row0 = d2b + (long long)iy0 * WW;
        const float* row1 = d2b + (long long)iy1 * WW;
        float rp0 = fmaf(q21, y0f, q22);   // row-dependent part of d1_calc
        float rp1 = fmaf(q21, y1f, q22);

        float Ia = corner_val(row0, ix0, rp0, q20, w2z);
        float Ib = corner_val(row1, ix0, rp1, q20, w2z);
        float Ic = corner_val(row0, ix1, rp0, q20, w2z);
        float Id = corner_val(row1, ix1, rp1, q20, w2z);

        float r = wa * Ia + wb * Ib + wc * Ic + wd * Id;
        out[pix] = r;
    }
}

extern "C" void kernel_launch(void* const* d_in, const int* in_sizes, int n_in,
                              void* d_out, int out_size) {
    const float* d1   = (const float*)d_in[0];
    const float* d2   = (const float*)d_in[1];
    const float* tr   = (const float*)d_in[2];
    const float* rot  = (const float*)d_in[3];
    const float* intr = (const float*)d_in[4];
    float* out = (float*)d_out;

    precompute_kernel<<<1, BB>>>(tr, rot, intr);

    const long long total = (long long)BB * HH * WW;   // 20,971,520
    // each block: 8 warps * 128 pixels = 1024 pixels
    const int blocks = (int)(total / 1024);            // 20480
    depth_warp_kernel<<<blocks, 256>>>(d1, d2, out);
}